// round 14
// baseline (speedup 1.0000x reference)
#include <cuda_runtime.h>
#include <cuda_fp16.h>
#include <math.h>
#include <stdint.h>

#define D_MODEL 512
#define D_FF    512
#define N_EXP   16
#define TOPK    3
#define MAX_T   2048
#define HROWS   (MAX_T + MAX_T * TOPK + 128)

#define TM   128
#define KC   64                 // fp16 elements per K chunk (128 bytes/row)
#define NCH  8                  // 512 / 64
#define TILE_A  (TM * 128)      // 16 KB (A tile: 128 rows x 128B)
#define OFF_B   TILE_A          // B tile: 256 rows x 128B = 32 KB
#define STAGE_B (3 * TILE_A)    // 48 KB per stage
#define NSTG 3
#define DYN_B   (NSTG * STAGE_B + 1024)

#define SWZ(o) ((o) ^ (((o) >> 3) & 0x70))

// ---------------- static scratch ----------------
__device__ int   g_cnt[N_EXP];
__device__ int   g_list[N_EXP * MAX_T];
__device__ float g_gate[N_EXP * MAX_T];

__device__ __align__(256) __half g_xw[MAX_T * D_MODEL];
__device__ __align__(256) __half g_sguw[2 * D_FF * D_MODEL];
__device__ __align__(256) __half g_sdnw[D_MODEL * D_FF];
__device__ __align__(256) __half g_eguw[N_EXP * 2 * D_FF * D_MODEL];
__device__ __align__(256) __half g_ednw[N_EXP * D_MODEL * D_FF];
__device__ __align__(256) __half g_H[(size_t)HROWS * D_FF];

// ---------------- PTX helpers ----------------
__device__ __forceinline__ uint32_t smem_u32(const void* p) {
    uint32_t a;
    asm("{ .reg .u64 t; cvta.to.shared.u64 t, %1; cvt.u32.u64 %0, t; }" : "=r"(a) : "l"(p));
    return a;
}
__device__ __forceinline__ void cp16(uint32_t s, const void* g) {
    asm volatile("cp.async.cg.shared.global [%0], [%1], 16;" :: "r"(s), "l"(g));
}
#define CP_COMMIT() asm volatile("cp.async.commit_group;")
#define CP_WAIT(n)  asm volatile("cp.async.wait_group %0;" :: "n"(n))

__device__ __forceinline__ void ldm4(uint32_t* r, uint32_t a) {
    asm volatile("ldmatrix.sync.aligned.m8n8.x4.shared.b16 {%0,%1,%2,%3}, [%4];"
                 : "=r"(r[0]), "=r"(r[1]), "=r"(r[2]), "=r"(r[3]) : "r"(a));
}
__device__ __forceinline__ void mma16816(float* c, const uint32_t* a, uint32_t b0, uint32_t b1) {
    asm volatile("mma.sync.aligned.m16n8k16.row.col.f32.f16.f16.f32 "
                 "{%0,%1,%2,%3}, {%4,%5,%6,%7}, {%8,%9}, {%0,%1,%2,%3};"
                 : "+f"(c[0]), "+f"(c[1]), "+f"(c[2]), "+f"(c[3])
                 : "r"(a[0]), "r"(a[1]), "r"(a[2]), "r"(a[3]), "r"(b0), "r"(b1));
}

// ---------------- small kernels ----------------
__global__ void reset_kernel() {
    if (threadIdx.x < N_EXP) g_cnt[threadIdx.x] = 0;
}

// segmented fp32 -> fp16 conversion (16 elts/thread); 3 segments
__global__ __launch_bounds__(256) void conv3_kernel(
    const float* __restrict__ s0, __half* __restrict__ d0, int n0,
    const float* __restrict__ s1, __half* __restrict__ d1, int n1,
    const float* __restrict__ s2, __half* __restrict__ d2, int n2)
{
    int total  = n0 + n1 + n2;
    int stride = gridDim.x * 256 * 16;
    for (int i0 = (blockIdx.x * 256 + threadIdx.x) * 16; i0 < total; i0 += stride) {
        const float* src;
        __half* dst;
        int off = i0;
        if (off < n0)              { src = s0; dst = d0; }
        else if ((off -= n0) < n1) { src = s1; dst = d1; }
        else { off -= n1;            src = s2; dst = d2; }
        float4 v[4];
#pragma unroll
        for (int q = 0; q < 4; q++) v[q] = *(const float4*)(src + off + q * 4);
        uint2 o[4];
#pragma unroll
        for (int q = 0; q < 4; q++) {
            __half2 p0 = __floats2half2_rn(v[q].x, v[q].y);
            __half2 p1 = __floats2half2_rn(v[q].z, v[q].w);
            o[q].x = *(uint32_t*)&p0;
            o[q].y = *(uint32_t*)&p1;
        }
        *(uint4*)(dst + off)     = make_uint4(o[0].x, o[0].y, o[1].x, o[1].y);
        *(uint4*)(dst + off + 8) = make_uint4(o[2].x, o[2].y, o[3].x, o[3].y);
    }
}

// Router: 16 tokens/block, 2 tokens/warp. gate_w staged in smem; all 32
// (token, expert) partials reduced in one 5-round butterfly; lanes 0/1 do top-k.
__global__ __launch_bounds__(256) void router_kernel(
    const float* __restrict__ x, const float* __restrict__ gw,
    const float* __restrict__ bias, int T)
{
    __shared__ float w_s[N_EXP * D_MODEL];   // 32 KB

    int tid = threadIdx.x;
#pragma unroll
    for (int j = 0; j < 8; j++) {
        int idx = (tid + j * 256) * 4;
        *(float4*)(w_s + idx) = *(const float4*)(gw + idx);
    }
    __syncthreads();

    int w    = tid >> 5;
    int lane = tid & 31;
    int t0   = blockIdx.x * 16 + w * 2;
    if (t0 >= T) return;

    const float* xr0 = x + (size_t)t0 * D_MODEL;
    const float* xr1 = x + (size_t)(t0 + 1) * D_MODEL;
    float xv0[16], xv1[16];
#pragma unroll
    for (int i = 0; i < 16; i++) {
        xv0[i] = xr0[lane + 32 * i];
        xv1[i] = xr1[lane + 32 * i];
    }

    float p0[N_EXP] = {}, p1[N_EXP] = {};
#pragma unroll
    for (int i = 0; i < 16; i++) {
#pragma unroll
        for (int e = 0; e < N_EXP; e++) {
            float wv = w_s[e * D_MODEL + lane + 32 * i];
            p0[e] += xv0[i] * wv;
            p1[e] += xv1[i] * wv;
        }
    }
#pragma unroll
    for (int o = 16; o; o >>= 1) {
#pragma unroll
        for (int e = 0; e < N_EXP; e++) {
            p0[e] += __shfl_xor_sync(0xffffffffu, p0[e], o);
            p1[e] += __shfl_xor_sync(0xffffffffu, p1[e], o);
        }
    }

    if (lane < 2) {
        int t = t0 + lane;
        float aff[N_EXP], sc[N_EXP];
        bool used[N_EXP];
#pragma unroll
        for (int e = 0; e < N_EXP; e++) {
            float logit = (lane == 0) ? p0[e] : p1[e];
            aff[e] = 1.f / (1.f + expf(-logit));
            sc[e]  = aff[e] + bias[e];
            used[e] = false;
        }
        int   sel[TOPK];
        float sa[TOPK];
        float ssum = 0.f;
        for (int k = 0; k < TOPK; k++) {
            int best = -1; float bv = -1e30f;
            for (int e = 0; e < N_EXP; e++)
                if (!used[e] && sc[e] > bv) { bv = sc[e]; best = e; }
            used[best] = true;
            sel[k] = best; sa[k] = aff[best]; ssum += aff[best];
        }
        float inv = 1.f / (ssum + 1e-9f);
        for (int k = 0; k < TOPK; k++) {
            int e   = sel[k];
            int pos = atomicAdd(&g_cnt[e], 1);
            g_list[e * MAX_T + pos] = t;
            g_gate[e * MAX_T + pos] = sa[k] * inv;
        }
    }
}

// ---------------- GEMM 1: x @ Wgu^T -> SwiGLU -> H (fp16) ----------------
// Block: 128 rows x 128 features. B tile = 256 interleaved rows (2j=gate f0+j, 2j+1=up f0+j).
// 8 warps as 2(M) x 4(N): warp tile 64 rows x 64 B-rows (32 features).
__global__ __launch_bounds__(256, 1) void gu_mma(int T)
{
    __shared__ int   tok_s[TM];
    __shared__ float gsc_s[TM];
    __shared__ int   off_s;
    extern __shared__ __align__(16) char dynraw[];

    int z  = blockIdx.z;
    int m0 = blockIdx.x * TM;
    int f0 = blockIdx.y * 128;
    int tid = threadIdx.x, wid = tid >> 5, lane = tid & 31;
    int warpM = wid >> 2, warpN = wid & 3;

    int cnt;
    const __half* W;
    if (z < N_EXP) {
        int c = g_cnt[z];
        if (m0 >= c) return;
        cnt = min(TM, c - m0);
        W   = g_eguw + (size_t)z * 2 * D_FF * D_MODEL;
        if (tid < TM) {
            if (tid < cnt) {
                tok_s[tid] = g_list[z * MAX_T + m0 + tid];
                gsc_s[tid] = g_gate[z * MAX_T + m0 + tid];
            } else { tok_s[tid] = 0; gsc_s[tid] = 0.f; }
        }
        if (wid == 0) {  // prefix: off = sum_{e<z} g_cnt[e]
            int v = (lane < z) ? g_cnt[lane] : 0;
#pragma unroll
            for (int o = 16; o; o >>= 1) v += __shfl_xor_sync(0xffffffffu, v, o);
            if (lane == 0) off_s = v;
        }
    } else {
        if (m0 >= T) return;
        cnt = min(TM, T - m0);
        W   = g_sguw;
        if (tid < TM) { tok_s[tid] = m0 + tid; gsc_s[tid] = 1.f; }
        if (tid == 0) off_s = 0;
    }
    __syncthreads();
    int hbase = (z < N_EXP) ? (MAX_T + off_s + m0) : m0;

    char*    dynp = (char*)(((uintptr_t)dynraw + 1023) & ~(uintptr_t)1023);
    uint32_t sb   = smem_u32(dynp);

    auto load_stage = [&](int s) {
        int kk = s * KC;
        uint32_t base = sb + (s % NSTG) * STAGE_B;
#pragma unroll
        for (int j = 0; j < 4; j++) {
            int w_ = tid + j * 256;
            int row = w_ >> 3, col = w_ & 7;
            uint32_t so = SWZ(row * 128 + col * 16);
            cp16(base + so, g_xw + (size_t)tok_s[row] * D_MODEL + kk + col * 8);
        }
#pragma unroll
        for (int j = 0; j < 8; j++) {
            int w_ = tid + j * 256;
            int row = w_ >> 3, col = w_ & 7;           // row 0..255
            uint32_t so = SWZ(row * 128 + col * 16);
            int wr = (row & 1) ? (D_FF + f0 + (row >> 1)) : (f0 + (row >> 1));
            cp16(base + OFF_B + so, W + (size_t)wr * D_MODEL + kk + col * 8);
        }
        CP_COMMIT();
    };

    float acc[4][8][4] = {};

    load_stage(0);
    load_stage(1);
    for (int s = 0; s < NCH; s++) {
        if (s + 2 < NCH)      { load_stage(s + 2); CP_WAIT(2); }
        else if (s + 1 < NCH) { CP_WAIT(1); }
        else                  { CP_WAIT(0); }
        __syncthreads();
        uint32_t base = sb + (s % NSTG) * STAGE_B;
#pragma unroll
        for (int ks = 0; ks < 4; ks++) {
            int kb = ks * 32 + (lane >> 4) * 16;
            uint32_t a[4][4], br[4][4];
            int arow = warpM * 64 + (lane & 15);
            int brow = warpN * 64 + (lane & 15);
#pragma unroll
            for (int h = 0; h < 4; h++)
                ldm4(br[h], base + OFF_B + SWZ((brow + h * 16) * 128 + kb));
#pragma unroll
            for (int mf = 0; mf < 4; mf++)
                ldm4(a[mf], base + SWZ((arow + mf * 16) * 128 + kb));
#pragma unroll
            for (int mf = 0; mf < 4; mf++)
#pragma unroll
                for (int h = 0; h < 4; h++)
#pragma unroll
                    for (int hf = 0; hf < 2; hf++)
                        mma16816(acc[mf][h * 2 + hf], a[mf], br[h][hf], br[h][hf + 2]);
        }
        __syncthreads();
    }

    // epilogue: (c even, c odd) = (gate, up) of one feature
#pragma unroll
    for (int mf = 0; mf < 4; mf++) {
        int rbase = warpM * 64 + mf * 16 + (lane >> 2);
#pragma unroll
        for (int rr = 0; rr < 2; rr++) {
            int r = rbase + rr * 8;
            if (r < cnt) {
                float gsc = gsc_s[r];
                size_t hrow = (size_t)(hbase + r) * D_FF;
#pragma unroll
                for (int h = 0; h < 4; h++)
#pragma unroll
                    for (int hf = 0; hf < 2; hf++) {
                        int nf = h * 2 + hf;
                        float g = acc[mf][nf][rr * 2 + 0];
                        float u = acc[mf][nf][rr * 2 + 1];
                        float hv = g / (1.f + __expf(-g)) * u * gsc;
                        int f = f0 + warpN * 32 + h * 8 + hf * 4 + (lane & 3);
                        g_H[hrow + f] = __float2half_rn(hv);
                    }
            }
        }
    }
}

// ---------------- GEMM 2: H @ Wd^T -> atomicAdd out ----------------
// Block: 128 rows x 256 output cols (256 B rows). Warp tile 64 x 64.
__global__ __launch_bounds__(256, 1) void down_mma(float* __restrict__ out, int T)
{
    __shared__ int tok_s[TM];
    __shared__ int off_s;
    extern __shared__ __align__(16) char dynraw[];

    int z  = blockIdx.z;
    int m0 = blockIdx.x * TM;
    int d0 = blockIdx.y * 256;
    int tid = threadIdx.x, wid = tid >> 5, lane = tid & 31;
    int warpM = wid >> 2, warpN = wid & 3;

    int cnt;
    const __half* W;
    if (z < N_EXP) {
        int c = g_cnt[z];
        if (m0 >= c) return;
        cnt = min(TM, c - m0);
        W   = g_ednw + (size_t)z * D_MODEL * D_FF;
        if (tid < TM) tok_s[tid] = (tid < cnt) ? g_list[z * MAX_T + m0 + tid] : 0;
        if (wid == 0) {
            int v = (lane < z) ? g_cnt[lane] : 0;
#pragma unroll
            for (int o = 16; o; o >>= 1) v += __shfl_xor_sync(0xffffffffu, v, o);
            if (lane == 0) off_s = v;
        }
    } else {
        if (m0 >= T) return;
        cnt = min(TM, T - m0);
        W   = g_sdnw;
        if (tid < TM) tok_s[tid] = m0 + tid;
        if (tid == 0) off_s = 0;
    }
    __syncthreads();
    int hbase = (z < N_EXP) ? (MAX_T + off_s + m0) : m0;

    char*    dynp = (char*)(((uintptr_t)dynraw + 1023) & ~(uintptr_t)1023);
    uint32_t sb   = smem_u32(dynp);

    auto load_stage = [&](int s) {
        int kk = s * KC;
        uint32_t base = sb + (s % NSTG) * STAGE_B;
#pragma unroll
        for (int j = 0; j < 4; j++) {
            int w_ = tid + j * 256;
            int row = w_ >> 3, col = w_ & 7;
            uint32_t so = SWZ(row * 128 + col * 16);
            cp16(base + so, g_H + (size_t)(hbase + row) * D_FF + kk + col * 8);
        }
#pragma unroll
        for (int j = 0; j < 8; j++) {
            int w_ = tid + j * 256;
            int row = w_ >> 3, col = w_ & 7;           // row 0..255
            uint32_t so = SWZ(row * 128 + col * 16);
            cp16(base + OFF_B + so, W + (size_t)(d0 + row) * D_FF + kk + col * 8);
        }
        CP_COMMIT();
    };

    float acc[4][8][4] = {};

    load_stage(0);
    load_stage(1);
    for (int s = 0; s < NCH; s++) {
        if (s + 2 < NCH)      { load_stage(s + 2); CP_WAIT(2); }
        else if (s + 1 < NCH) { CP_WAIT(1); }
        else                  { CP_WAIT(0); }
        __syncthreads();
        uint32_t base = sb + (s % NSTG) * STAGE_B;
#pragma unroll
        for (int ks = 0; ks < 4; ks++) {
            int kb = ks * 32 + (lane >> 4) * 16;
            uint32_t a[4][4], br[4][4];
            int arow = warpM * 64 + (lane & 15);
            int brow = warpN * 64 + (lane & 15);
#pragma unroll
            for (int h = 0; h < 4; h++)
                ldm4(br[h], base + OFF_B + SWZ((brow + h * 16) * 128 + kb));
#pragma unroll
            for (int mf = 0; mf < 4; mf++)
                ldm4(a[mf], base + SWZ((arow + mf * 16) * 128 + kb));
#pragma unroll
            for (int mf = 0; mf < 4; mf++)
#pragma unroll
                for (int h = 0; h < 4; h++)
#pragma unroll
                    for (int hf = 0; hf < 2; hf++)
                        mma16816(acc[mf][h * 2 + hf], a[mf], br[h][hf], br[h][hf + 2]);
        }
        __syncthreads();
    }

#pragma unroll
    for (int mf = 0; mf < 4; mf++) {
        int rbase = warpM * 64 + mf * 16 + (lane >> 2);
#pragma unroll
        for (int rr = 0; rr < 2; rr++) {
            int r = rbase + rr * 8;
            if (r < cnt) {
                float* orow = out + (size_t)tok_s[r] * D_MODEL;
#pragma unroll
                for (int h = 0; h < 4; h++)
#pragma unroll
                    for (int hf = 0; hf < 2; hf++) {
                        int nf = h * 2 + hf;
                        int c  = d0 + warpN * 64 + h * 16 + hf * 8 + (lane & 3) * 2;
                        atomicAdd(orow + c,     acc[mf][nf][rr * 2 + 0]);
                        atomicAdd(orow + c + 1, acc[mf][nf][rr * 2 + 1]);
                    }
            }
        }
    }
}

// ---------------- launch ----------------
extern "C" void kernel_launch(void* const* d_in, const int* in_sizes, int n_in,
                              void* d_out, int out_size)
{
    const float* x    = (const float*)d_in[0];
    const float* gw   = (const float*)d_in[1];
    const float* bias = (const float*)d_in[2];
    const float* sgu  = (const float*)d_in[3];
    const float* sdn  = (const float*)d_in[4];
    const float* egu  = (const float*)d_in[5];
    const float* edn  = (const float*)d_in[6];
    float* out = (float*)d_out;
    int T = in_sizes[0] / D_MODEL;

    cudaFuncSetAttribute(gu_mma,   cudaFuncAttributeMaxDynamicSharedMemorySize, DYN_B);
    cudaFuncSetAttribute(down_mma, cudaFuncAttributeMaxDynamicSharedMemorySize, DYN_B);

    void *xw, *sguw, *sdnw, *eguw, *ednw;
    cudaGetSymbolAddress(&xw,   g_xw);
    cudaGetSymbolAddress(&sguw, g_sguw); cudaGetSymbolAddress(&sdnw, g_sdnw);
    cudaGetSymbolAddress(&eguw, g_eguw); cudaGetSymbolAddress(&ednw, g_ednw);

    int nx   = T * D_MODEL;
    int ngu  = 2 * D_FF * D_MODEL;
    int ndn  = D_MODEL * D_FF;
    int negu = N_EXP * 2 * D_FF * D_MODEL;
    int nedn = N_EXP * D_MODEL * D_FF;

    cudaStream_t s1;
    cudaStreamCreate(&s1);
    cudaEvent_t e0, e_gu, e_dn;
    cudaEventCreateWithFlags(&e0,   cudaEventDisableTiming);
    cudaEventCreateWithFlags(&e_gu, cudaEventDisableTiming);
    cudaEventCreateWithFlags(&e_dn, cudaEventDisableTiming);

    // main stream first: routing chain (small, smem/FMA-bound; grabs SMs first)
    reset_kernel<<<1, 32>>>();
    router_kernel<<<(T + 15) / 16, 256>>>(x, gw, bias, T);

    // side stream: gu-side conversions (DRAM-bound; coexists with router),
    // then dn-side conversions + memset (overlap with gu_mma)
    cudaEventRecord(e0, 0);
    cudaStreamWaitEvent(s1, e0, 0);
    int ngu_tot = nx + ngu + negu;
    conv3_kernel<<<(ngu_tot / 16 + 255) / 256, 256, 0, s1>>>(
        x,   (__half*)xw,   nx,
        sgu, (__half*)sguw, ngu,
        egu, (__half*)eguw, negu);
    cudaEventRecord(e_gu, s1);
    conv3_kernel<<<((ndn + nedn) / 16 + 255) / 256, 256, 0, s1>>>(
        sdn, (__half*)sdnw, ndn,
        edn, (__half*)ednw, nedn,
        sdn, (__half*)sdnw, 0);
    cudaMemsetAsync(out, 0, (size_t)out_size * sizeof(float), s1);
    cudaEventRecord(e_dn, s1);

    cudaStreamWaitEvent(0, e_gu, 0);
    gu_mma<<<dim3(MAX_T / TM, D_FF / 128, N_EXP + 1), 256, DYN_B>>>(T);

    cudaStreamWaitEvent(0, e_dn, 0);
    down_mma<<<dim3(MAX_T / TM, D_MODEL / 256, N_EXP + 1), 256, DYN_B>>>(out, T);

    cudaEventDestroy(e0);
    cudaEventDestroy(e_gu);
    cudaEventDestroy(e_dn);
    cudaStreamDestroy(s1);
}

// round 15
// speedup vs baseline: 1.4782x; 1.4782x over previous
#include <cuda_runtime.h>
#include <cuda_fp16.h>
#include <math.h>
#include <stdint.h>

#define D_MODEL 512
#define D_FF    512
#define N_EXP   16
#define TOPK    3
#define MAX_T   2048
#define HROWS   (MAX_T + MAX_T * TOPK + 128)

#define TM   128
#define KC   64                 // fp16 elements per K chunk (128 bytes/row)
#define NCH  8                  // 512 / 64
#define TILE_A  (TM * 128)      // 16 KB (A tile: 128 rows x 128B)
#define OFF_B   TILE_A          // B tile: 256 rows x 128B = 32 KB
#define STAGE_B (3 * TILE_A)    // 48 KB per stage
#define NSTG 3
#define DYN_B   (NSTG * STAGE_B + 1024)

#define SWZ(o) ((o) ^ (((o) >> 3) & 0x70))

// ---------------- static scratch ----------------
__device__ int   g_cnt[N_EXP];
__device__ int   g_list[N_EXP * MAX_T];
__device__ float g_gate[N_EXP * MAX_T];

__device__ __align__(256) __half g_xw[MAX_T * D_MODEL];
__device__ __align__(256) __half g_sguw[2 * D_FF * D_MODEL];
__device__ __align__(256) __half g_sdnw[D_MODEL * D_FF];
__device__ __align__(256) __half g_eguw[N_EXP * 2 * D_FF * D_MODEL];
__device__ __align__(256) __half g_ednw[N_EXP * D_MODEL * D_FF];
__device__ __align__(256) __half g_H[(size_t)HROWS * D_FF];

// ---------------- PTX helpers ----------------
__device__ __forceinline__ uint32_t smem_u32(const void* p) {
    uint32_t a;
    asm("{ .reg .u64 t; cvta.to.shared.u64 t, %1; cvt.u32.u64 %0, t; }" : "=r"(a) : "l"(p));
    return a;
}
__device__ __forceinline__ void cp16(uint32_t s, const void* g) {
    asm volatile("cp.async.cg.shared.global [%0], [%1], 16;" :: "r"(s), "l"(g));
}
#define CP_COMMIT() asm volatile("cp.async.commit_group;")
#define CP_WAIT(n)  asm volatile("cp.async.wait_group %0;" :: "n"(n))

__device__ __forceinline__ void ldm4(uint32_t* r, uint32_t a) {
    asm volatile("ldmatrix.sync.aligned.m8n8.x4.shared.b16 {%0,%1,%2,%3}, [%4];"
                 : "=r"(r[0]), "=r"(r[1]), "=r"(r[2]), "=r"(r[3]) : "r"(a));
}
__device__ __forceinline__ void mma16816(float* c, const uint32_t* a, uint32_t b0, uint32_t b1) {
    asm volatile("mma.sync.aligned.m16n8k16.row.col.f32.f16.f16.f32 "
                 "{%0,%1,%2,%3}, {%4,%5,%6,%7}, {%8,%9}, {%0,%1,%2,%3};"
                 : "+f"(c[0]), "+f"(c[1]), "+f"(c[2]), "+f"(c[3])
                 : "r"(a[0]), "r"(a[1]), "r"(a[2]), "r"(a[3]), "r"(b0), "r"(b1));
}

// ---------------- small kernels ----------------
__global__ void reset_kernel() {
    if (threadIdx.x < N_EXP) g_cnt[threadIdx.x] = 0;
}

// segmented fp32 -> fp16 conversion (16 elts/thread); 3 segments
__global__ __launch_bounds__(256) void conv3_kernel(
    const float* __restrict__ s0, __half* __restrict__ d0, int n0,
    const float* __restrict__ s1, __half* __restrict__ d1, int n1,
    const float* __restrict__ s2, __half* __restrict__ d2, int n2)
{
    int total  = n0 + n1 + n2;
    int stride = gridDim.x * 256 * 16;
    for (int i0 = (blockIdx.x * 256 + threadIdx.x) * 16; i0 < total; i0 += stride) {
        const float* src;
        __half* dst;
        int off = i0;
        if (off < n0)              { src = s0; dst = d0; }
        else if ((off -= n0) < n1) { src = s1; dst = d1; }
        else { off -= n1;            src = s2; dst = d2; }
        float4 v[4];
#pragma unroll
        for (int q = 0; q < 4; q++) v[q] = *(const float4*)(src + off + q * 4);
        uint2 o[4];
#pragma unroll
        for (int q = 0; q < 4; q++) {
            __half2 p0 = __floats2half2_rn(v[q].x, v[q].y);
            __half2 p1 = __floats2half2_rn(v[q].z, v[q].w);
            o[q].x = *(uint32_t*)&p0;
            o[q].y = *(uint32_t*)&p1;
        }
        *(uint4*)(dst + off)     = make_uint4(o[0].x, o[0].y, o[1].x, o[1].y);
        *(uint4*)(dst + off + 8) = make_uint4(o[2].x, o[2].y, o[3].x, o[3].y);
    }
}

// Router: 16 tokens/block, 2 tokens/warp. gate_w staged in smem; all 32
// (token, expert) partials reduced in one 5-round butterfly; lanes 0/1 do top-k.
__global__ __launch_bounds__(256) void router_kernel(
    const float* __restrict__ x, const float* __restrict__ gw,
    const float* __restrict__ bias, int T)
{
    __shared__ float w_s[N_EXP * D_MODEL];   // 32 KB

    int tid = threadIdx.x;
#pragma unroll
    for (int j = 0; j < 8; j++) {
        int idx = (tid + j * 256) * 4;
        *(float4*)(w_s + idx) = *(const float4*)(gw + idx);
    }
    __syncthreads();

    int w    = tid >> 5;
    int lane = tid & 31;
    int t0   = blockIdx.x * 16 + w * 2;
    if (t0 >= T) return;

    const float* xr0 = x + (size_t)t0 * D_MODEL;
    const float* xr1 = x + (size_t)(t0 + 1) * D_MODEL;
    float xv0[16], xv1[16];
#pragma unroll
    for (int i = 0; i < 16; i++) {
        xv0[i] = xr0[lane + 32 * i];
        xv1[i] = xr1[lane + 32 * i];
    }

    float p0[N_EXP] = {}, p1[N_EXP] = {};
#pragma unroll
    for (int i = 0; i < 16; i++) {
#pragma unroll
        for (int e = 0; e < N_EXP; e++) {
            float wv = w_s[e * D_MODEL + lane + 32 * i];
            p0[e] += xv0[i] * wv;
            p1[e] += xv1[i] * wv;
        }
    }
#pragma unroll
    for (int o = 16; o; o >>= 1) {
#pragma unroll
        for (int e = 0; e < N_EXP; e++) {
            p0[e] += __shfl_xor_sync(0xffffffffu, p0[e], o);
            p1[e] += __shfl_xor_sync(0xffffffffu, p1[e], o);
        }
    }

    if (lane < 2) {
        int t = t0 + lane;
        float aff[N_EXP], sc[N_EXP];
        bool used[N_EXP];
#pragma unroll
        for (int e = 0; e < N_EXP; e++) {
            float logit = (lane == 0) ? p0[e] : p1[e];
            aff[e] = 1.f / (1.f + expf(-logit));
            sc[e]  = aff[e] + bias[e];
            used[e] = false;
        }
        int   sel[TOPK];
        float sa[TOPK];
        float ssum = 0.f;
        for (int k = 0; k < TOPK; k++) {
            int best = -1; float bv = -1e30f;
            for (int e = 0; e < N_EXP; e++)
                if (!used[e] && sc[e] > bv) { bv = sc[e]; best = e; }
            used[best] = true;
            sel[k] = best; sa[k] = aff[best]; ssum += aff[best];
        }
        float inv = 1.f / (ssum + 1e-9f);
        for (int k = 0; k < TOPK; k++) {
            int e   = sel[k];
            int pos = atomicAdd(&g_cnt[e], 1);
            g_list[e * MAX_T + pos] = t;
            g_gate[e * MAX_T + pos] = sa[k] * inv;
        }
    }
}

// ---------------- GEMM 1: x @ Wgu^T -> SwiGLU -> H (fp16) ----------------
// Block: 128 rows x 128 features. B tile = 256 interleaved rows (2j=gate f0+j, 2j+1=up f0+j).
// 8 warps as 2(M) x 4(N): warp tile 64 rows x 64 B-rows (32 features).
__global__ __launch_bounds__(256, 1) void gu_mma(int T)
{
    __shared__ int   tok_s[TM];
    __shared__ float gsc_s[TM];
    __shared__ int   off_s;
    extern __shared__ __align__(16) char dynraw[];

    int z  = blockIdx.z;
    int m0 = blockIdx.x * TM;
    int f0 = blockIdx.y * 128;
    int tid = threadIdx.x, wid = tid >> 5, lane = tid & 31;
    int warpM = wid >> 2, warpN = wid & 3;

    int cnt;
    const __half* W;
    if (z < N_EXP) {
        int c = g_cnt[z];
        if (m0 >= c) return;
        cnt = min(TM, c - m0);
        W   = g_eguw + (size_t)z * 2 * D_FF * D_MODEL;
        if (tid < TM) {
            if (tid < cnt) {
                tok_s[tid] = g_list[z * MAX_T + m0 + tid];
                gsc_s[tid] = g_gate[z * MAX_T + m0 + tid];
            } else { tok_s[tid] = 0; gsc_s[tid] = 0.f; }
        }
        if (wid == 0) {  // prefix: off = sum_{e<z} g_cnt[e]
            int v = (lane < z) ? g_cnt[lane] : 0;
#pragma unroll
            for (int o = 16; o; o >>= 1) v += __shfl_xor_sync(0xffffffffu, v, o);
            if (lane == 0) off_s = v;
        }
    } else {
        if (m0 >= T) return;
        cnt = min(TM, T - m0);
        W   = g_sguw;
        if (tid < TM) { tok_s[tid] = m0 + tid; gsc_s[tid] = 1.f; }
        if (tid == 0) off_s = 0;
    }
    __syncthreads();
    int hbase = (z < N_EXP) ? (MAX_T + off_s + m0) : m0;

    char*    dynp = (char*)(((uintptr_t)dynraw + 1023) & ~(uintptr_t)1023);
    uint32_t sb   = smem_u32(dynp);

    auto load_stage = [&](int s) {
        int kk = s * KC;
        uint32_t base = sb + (s % NSTG) * STAGE_B;
#pragma unroll
        for (int j = 0; j < 4; j++) {
            int w_ = tid + j * 256;
            int row = w_ >> 3, col = w_ & 7;
            uint32_t so = SWZ(row * 128 + col * 16);
            cp16(base + so, g_xw + (size_t)tok_s[row] * D_MODEL + kk + col * 8);
        }
#pragma unroll
        for (int j = 0; j < 8; j++) {
            int w_ = tid + j * 256;
            int row = w_ >> 3, col = w_ & 7;           // row 0..255
            uint32_t so = SWZ(row * 128 + col * 16);
            int wr = (row & 1) ? (D_FF + f0 + (row >> 1)) : (f0 + (row >> 1));
            cp16(base + OFF_B + so, W + (size_t)wr * D_MODEL + kk + col * 8);
        }
        CP_COMMIT();
    };

    float acc[4][8][4] = {};

    load_stage(0);
    load_stage(1);
    for (int s = 0; s < NCH; s++) {
        if (s + 2 < NCH)      { load_stage(s + 2); CP_WAIT(2); }
        else if (s + 1 < NCH) { CP_WAIT(1); }
        else                  { CP_WAIT(0); }
        __syncthreads();
        uint32_t base = sb + (s % NSTG) * STAGE_B;
#pragma unroll
        for (int ks = 0; ks < 4; ks++) {
            int kb = ks * 32 + (lane >> 4) * 16;
            uint32_t a[4][4], br[4][4];
            int arow = warpM * 64 + (lane & 15);
            int brow = warpN * 64 + (lane & 15);
#pragma unroll
            for (int h = 0; h < 4; h++)
                ldm4(br[h], base + OFF_B + SWZ((brow + h * 16) * 128 + kb));
#pragma unroll
            for (int mf = 0; mf < 4; mf++)
                ldm4(a[mf], base + SWZ((arow + mf * 16) * 128 + kb));
#pragma unroll
            for (int mf = 0; mf < 4; mf++)
#pragma unroll
                for (int h = 0; h < 4; h++)
#pragma unroll
                    for (int hf = 0; hf < 2; hf++)
                        mma16816(acc[mf][h * 2 + hf], a[mf], br[h][hf], br[h][hf + 2]);
        }
        __syncthreads();
    }

    // epilogue: (c even, c odd) = (gate, up) of one feature
#pragma unroll
    for (int mf = 0; mf < 4; mf++) {
        int rbase = warpM * 64 + mf * 16 + (lane >> 2);
#pragma unroll
        for (int rr = 0; rr < 2; rr++) {
            int r = rbase + rr * 8;
            if (r < cnt) {
                float gsc = gsc_s[r];
                size_t hrow = (size_t)(hbase + r) * D_FF;
#pragma unroll
                for (int h = 0; h < 4; h++)
#pragma unroll
                    for (int hf = 0; hf < 2; hf++) {
                        int nf = h * 2 + hf;
                        float g = acc[mf][nf][rr * 2 + 0];
                        float u = acc[mf][nf][rr * 2 + 1];
                        float hv = g / (1.f + __expf(-g)) * u * gsc;
                        int f = f0 + warpN * 32 + h * 8 + hf * 4 + (lane & 3);
                        g_H[hrow + f] = __float2half_rn(hv);
                    }
            }
        }
    }
}

// ---------------- GEMM 2: H @ Wd^T -> atomicAdd out ----------------
// Block: 128 rows x 256 output cols (256 B rows). Warp tile 64 x 64.
__global__ __launch_bounds__(256, 1) void down_mma(float* __restrict__ out, int T)
{
    __shared__ int tok_s[TM];
    __shared__ int off_s;
    extern __shared__ __align__(16) char dynraw[];

    int z  = blockIdx.z;
    int m0 = blockIdx.x * TM;
    int d0 = blockIdx.y * 256;
    int tid = threadIdx.x, wid = tid >> 5, lane = tid & 31;
    int warpM = wid >> 2, warpN = wid & 3;

    int cnt;
    const __half* W;
    if (z < N_EXP) {
        int c = g_cnt[z];
        if (m0 >= c) return;
        cnt = min(TM, c - m0);
        W   = g_ednw + (size_t)z * D_MODEL * D_FF;
        if (tid < TM) tok_s[tid] = (tid < cnt) ? g_list[z * MAX_T + m0 + tid] : 0;
        if (wid == 0) {
            int v = (lane < z) ? g_cnt[lane] : 0;
#pragma unroll
            for (int o = 16; o; o >>= 1) v += __shfl_xor_sync(0xffffffffu, v, o);
            if (lane == 0) off_s = v;
        }
    } else {
        if (m0 >= T) return;
        cnt = min(TM, T - m0);
        W   = g_sdnw;
        if (tid < TM) tok_s[tid] = m0 + tid;
        if (tid == 0) off_s = 0;
    }
    __syncthreads();
    int hbase = (z < N_EXP) ? (MAX_T + off_s + m0) : m0;

    char*    dynp = (char*)(((uintptr_t)dynraw + 1023) & ~(uintptr_t)1023);
    uint32_t sb   = smem_u32(dynp);

    auto load_stage = [&](int s) {
        int kk = s * KC;
        uint32_t base = sb + (s % NSTG) * STAGE_B;
#pragma unroll
        for (int j = 0; j < 4; j++) {
            int w_ = tid + j * 256;
            int row = w_ >> 3, col = w_ & 7;
            uint32_t so = SWZ(row * 128 + col * 16);
            cp16(base + so, g_H + (size_t)(hbase + row) * D_FF + kk + col * 8);
        }
#pragma unroll
        for (int j = 0; j < 8; j++) {
            int w_ = tid + j * 256;
            int row = w_ >> 3, col = w_ & 7;           // row 0..255
            uint32_t so = SWZ(row * 128 + col * 16);
            cp16(base + OFF_B + so, W + (size_t)(d0 + row) * D_FF + kk + col * 8);
        }
        CP_COMMIT();
    };

    float acc[4][8][4] = {};

    load_stage(0);
    load_stage(1);
    for (int s = 0; s < NCH; s++) {
        if (s + 2 < NCH)      { load_stage(s + 2); CP_WAIT(2); }
        else if (s + 1 < NCH) { CP_WAIT(1); }
        else                  { CP_WAIT(0); }
        __syncthreads();
        uint32_t base = sb + (s % NSTG) * STAGE_B;
#pragma unroll
        for (int ks = 0; ks < 4; ks++) {
            int kb = ks * 32 + (lane >> 4) * 16;
            uint32_t a[4][4], br[4][4];
            int arow = warpM * 64 + (lane & 15);
            int brow = warpN * 64 + (lane & 15);
#pragma unroll
            for (int h = 0; h < 4; h++)
                ldm4(br[h], base + OFF_B + SWZ((brow + h * 16) * 128 + kb));
#pragma unroll
            for (int mf = 0; mf < 4; mf++)
                ldm4(a[mf], base + SWZ((arow + mf * 16) * 128 + kb));
#pragma unroll
            for (int mf = 0; mf < 4; mf++)
#pragma unroll
                for (int h = 0; h < 4; h++)
#pragma unroll
                    for (int hf = 0; hf < 2; hf++)
                        mma16816(acc[mf][h * 2 + hf], a[mf], br[h][hf], br[h][hf + 2]);
        }
        __syncthreads();
    }

#pragma unroll
    for (int mf = 0; mf < 4; mf++) {
        int rbase = warpM * 64 + mf * 16 + (lane >> 2);
#pragma unroll
        for (int rr = 0; rr < 2; rr++) {
            int r = rbase + rr * 8;
            if (r < cnt) {
                float* orow = out + (size_t)tok_s[r] * D_MODEL;
#pragma unroll
                for (int h = 0; h < 4; h++)
#pragma unroll
                    for (int hf = 0; hf < 2; hf++) {
                        int nf = h * 2 + hf;
                        int c  = d0 + warpN * 64 + h * 16 + hf * 8 + (lane & 3) * 2;
                        atomicAdd(orow + c,     acc[mf][nf][rr * 2 + 0]);
                        atomicAdd(orow + c + 1, acc[mf][nf][rr * 2 + 1]);
                    }
            }
        }
    }
}

// ---------------- launch ----------------
extern "C" void kernel_launch(void* const* d_in, const int* in_sizes, int n_in,
                              void* d_out, int out_size)
{
    const float* x    = (const float*)d_in[0];
    const float* gw   = (const float*)d_in[1];
    const float* bias = (const float*)d_in[2];
    const float* sgu  = (const float*)d_in[3];
    const float* sdn  = (const float*)d_in[4];
    const float* egu  = (const float*)d_in[5];
    const float* edn  = (const float*)d_in[6];
    float* out = (float*)d_out;
    int T = in_sizes[0] / D_MODEL;

    cudaFuncSetAttribute(gu_mma,   cudaFuncAttributeMaxDynamicSharedMemorySize, DYN_B);
    cudaFuncSetAttribute(down_mma, cudaFuncAttributeMaxDynamicSharedMemorySize, DYN_B);

    void *xw, *sguw, *sdnw, *eguw, *ednw;
    cudaGetSymbolAddress(&xw,   g_xw);
    cudaGetSymbolAddress(&sguw, g_sguw); cudaGetSymbolAddress(&sdnw, g_sdnw);
    cudaGetSymbolAddress(&eguw, g_eguw); cudaGetSymbolAddress(&ednw, g_ednw);

    int nx   = T * D_MODEL;
    int ngu  = 2 * D_FF * D_MODEL;
    int ndn  = D_MODEL * D_FF;
    int negu = N_EXP * 2 * D_FF * D_MODEL;
    int nedn = N_EXP * D_MODEL * D_FF;

    cudaStream_t s1;
    cudaStreamCreate(&s1);
    cudaEvent_t e0, e_gu, e_dn;
    cudaEventCreateWithFlags(&e0,   cudaEventDisableTiming);
    cudaEventCreateWithFlags(&e_gu, cudaEventDisableTiming);
    cudaEventCreateWithFlags(&e_dn, cudaEventDisableTiming);

    // fork FIRST: side stream starts conversions immediately, concurrent with
    // the router chain on the main stream
    cudaEventRecord(e0, 0);
    cudaStreamWaitEvent(s1, e0, 0);
    int ngu_tot = nx + ngu + negu;
    conv3_kernel<<<(ngu_tot / 16 + 255) / 256, 256, 0, s1>>>(
        x,   (__half*)xw,   nx,
        sgu, (__half*)sguw, ngu,
        egu, (__half*)eguw, negu);
    cudaEventRecord(e_gu, s1);
    conv3_kernel<<<((ndn + nedn) / 16 + 255) / 256, 256, 0, s1>>>(
        sdn, (__half*)sdnw, ndn,
        edn, (__half*)ednw, nedn,
        sdn, (__half*)sdnw, 0);
    cudaMemsetAsync(out, 0, (size_t)out_size * sizeof(float), s1);
    cudaEventRecord(e_dn, s1);

    // main stream: routing chain (hidden under conv_gu)
    reset_kernel<<<1, 32>>>();
    router_kernel<<<(T + 15) / 16, 256>>>(x, gw, bias, T);

    cudaStreamWaitEvent(0, e_gu, 0);
    gu_mma<<<dim3(MAX_T / TM, D_FF / 128, N_EXP + 1), 256, DYN_B>>>(T);

    cudaStreamWaitEvent(0, e_dn, 0);
    down_mma<<<dim3(MAX_T / TM, D_MODEL / 256, N_EXP + 1), 256, DYN_B>>>(out, T);

    cudaEventDestroy(e0);
    cudaEventDestroy(e_gu);
    cudaEventDestroy(e_dn);
    cudaStreamDestroy(s1);
}

// round 16
// speedup vs baseline: 1.5061x; 1.0189x over previous
#include <cuda_runtime.h>
#include <cuda_fp16.h>
#include <math.h>
#include <stdint.h>

#define D_MODEL 512
#define D_FF    512
#define N_EXP   16
#define TOPK    3
#define MAX_T   2048
#define HROWS   (MAX_T + MAX_T * TOPK + 128)

#define TM   128
#define KC   64                 // fp16 elements per K chunk (128 bytes/row)
#define NCH  8                  // 512 / 64
#define TILE_A  (TM * 128)      // 16 KB (A tile: 128 rows x 128B)
#define OFF_B   TILE_A          // B tile: 256 rows x 128B = 32 KB
#define STAGE_B (3 * TILE_A)    // 48 KB per stage
#define NSTG 3
#define DYN_B   (NSTG * STAGE_B + 1024)

#define SWZ(o) ((o) ^ (((o) >> 3) & 0x70))

// ---------------- static scratch ----------------
__device__ int   g_cnt[N_EXP];
__device__ int   g_list[N_EXP * MAX_T];
__device__ float g_gate[N_EXP * MAX_T];

__device__ __align__(256) __half g_xw[MAX_T * D_MODEL];
__device__ __align__(256) __half g_sguw[2 * D_FF * D_MODEL];
__device__ __align__(256) __half g_sdnw[D_MODEL * D_FF];
__device__ __align__(256) __half g_eguw[N_EXP * 2 * D_FF * D_MODEL];
__device__ __align__(256) __half g_ednw[N_EXP * D_MODEL * D_FF];
__device__ __align__(256) __half g_H[(size_t)HROWS * D_FF];

// ---------------- PTX helpers ----------------
__device__ __forceinline__ uint32_t smem_u32(const void* p) {
    uint32_t a;
    asm("{ .reg .u64 t; cvta.to.shared.u64 t, %1; cvt.u32.u64 %0, t; }" : "=r"(a) : "l"(p));
    return a;
}
__device__ __forceinline__ void cp16(uint32_t s, const void* g) {
    asm volatile("cp.async.cg.shared.global [%0], [%1], 16;" :: "r"(s), "l"(g));
}
#define CP_COMMIT() asm volatile("cp.async.commit_group;")
#define CP_WAIT(n)  asm volatile("cp.async.wait_group %0;" :: "n"(n))

__device__ __forceinline__ void ldm4(uint32_t* r, uint32_t a) {
    asm volatile("ldmatrix.sync.aligned.m8n8.x4.shared.b16 {%0,%1,%2,%3}, [%4];"
                 : "=r"(r[0]), "=r"(r[1]), "=r"(r[2]), "=r"(r[3]) : "r"(a));
}
__device__ __forceinline__ void mma16816(float* c, const uint32_t* a, uint32_t b0, uint32_t b1) {
    asm volatile("mma.sync.aligned.m16n8k16.row.col.f32.f16.f16.f32 "
                 "{%0,%1,%2,%3}, {%4,%5,%6,%7}, {%8,%9}, {%0,%1,%2,%3};"
                 : "+f"(c[0]), "+f"(c[1]), "+f"(c[2]), "+f"(c[3])
                 : "r"(a[0]), "r"(a[1]), "r"(a[2]), "r"(a[3]), "r"(b0), "r"(b1));
}

// ---------------- small kernels ----------------
__global__ void reset_kernel() {
    if (threadIdx.x < N_EXP) g_cnt[threadIdx.x] = 0;
}

// segmented fp32 -> fp16 conversion (16 elts/thread); 3 segments
__global__ __launch_bounds__(256) void conv3_kernel(
    const float* __restrict__ s0, __half* __restrict__ d0, int n0,
    const float* __restrict__ s1, __half* __restrict__ d1, int n1,
    const float* __restrict__ s2, __half* __restrict__ d2, int n2)
{
    int total  = n0 + n1 + n2;
    int stride = gridDim.x * 256 * 16;
    for (int i0 = (blockIdx.x * 256 + threadIdx.x) * 16; i0 < total; i0 += stride) {
        const float* src;
        __half* dst;
        int off = i0;
        if (off < n0)              { src = s0; dst = d0; }
        else if ((off -= n0) < n1) { src = s1; dst = d1; }
        else { off -= n1;            src = s2; dst = d2; }
        float4 v[4];
#pragma unroll
        for (int q = 0; q < 4; q++) v[q] = *(const float4*)(src + off + q * 4);
        uint2 o[4];
#pragma unroll
        for (int q = 0; q < 4; q++) {
            __half2 p0 = __floats2half2_rn(v[q].x, v[q].y);
            __half2 p1 = __floats2half2_rn(v[q].z, v[q].w);
            o[q].x = *(uint32_t*)&p0;
            o[q].y = *(uint32_t*)&p1;
        }
        *(uint4*)(dst + off)     = make_uint4(o[0].x, o[0].y, o[1].x, o[1].y);
        *(uint4*)(dst + off + 8) = make_uint4(o[2].x, o[2].y, o[3].x, o[3].y);
    }
}

// Router: 16 tokens/block (512 threads), 1 token/warp — no register spills.
// gate_w staged in smem; 16 expert partials per warp reduced in a 5-round
// butterfly (all experts simultaneously); lane 0 does top-k.
__global__ __launch_bounds__(512) void router_kernel(
    const float* __restrict__ x, const float* __restrict__ gw,
    const float* __restrict__ bias, int T)
{
    __shared__ float w_s[N_EXP * D_MODEL];   // 32 KB

    int tid = threadIdx.x;
#pragma unroll
    for (int j = 0; j < 4; j++) {
        int idx = (tid + j * 512) * 4;
        *(float4*)(w_s + idx) = *(const float4*)(gw + idx);
    }
    __syncthreads();

    int w    = tid >> 5;
    int lane = tid & 31;
    int t    = blockIdx.x * 16 + w;
    if (t >= T) return;

    const float* xr = x + (size_t)t * D_MODEL;
    float xv[16];
#pragma unroll
    for (int i = 0; i < 16; i++) xv[i] = xr[lane + 32 * i];

    float p[N_EXP] = {};
#pragma unroll
    for (int i = 0; i < 16; i++) {
#pragma unroll
        for (int e = 0; e < N_EXP; e++)
            p[e] += xv[i] * w_s[e * D_MODEL + lane + 32 * i];
    }
#pragma unroll
    for (int o = 16; o; o >>= 1) {
#pragma unroll
        for (int e = 0; e < N_EXP; e++)
            p[e] += __shfl_xor_sync(0xffffffffu, p[e], o);
    }

    if (lane == 0) {
        float aff[N_EXP], sc[N_EXP];
        bool used[N_EXP];
#pragma unroll
        for (int e = 0; e < N_EXP; e++) {
            aff[e] = 1.f / (1.f + expf(-p[e]));
            sc[e]  = aff[e] + bias[e];
            used[e] = false;
        }
        int   sel[TOPK];
        float sa[TOPK];
        float ssum = 0.f;
        for (int k = 0; k < TOPK; k++) {
            int best = -1; float bv = -1e30f;
            for (int e = 0; e < N_EXP; e++)
                if (!used[e] && sc[e] > bv) { bv = sc[e]; best = e; }
            used[best] = true;
            sel[k] = best; sa[k] = aff[best]; ssum += aff[best];
        }
        float inv = 1.f / (ssum + 1e-9f);
        for (int k = 0; k < TOPK; k++) {
            int e   = sel[k];
            int pos = atomicAdd(&g_cnt[e], 1);
            g_list[e * MAX_T + pos] = t;
            g_gate[e * MAX_T + pos] = sa[k] * inv;
        }
    }
}

// ---------------- GEMM 1: x @ Wgu^T -> SwiGLU -> H (fp16) ----------------
// Block: 128 rows x 128 features. B tile = 256 interleaved rows (2j=gate f0+j, 2j+1=up f0+j).
// 8 warps as 2(M) x 4(N): warp tile 64 rows x 64 B-rows (32 features).
__global__ __launch_bounds__(256, 1) void gu_mma(int T)
{
    __shared__ int   tok_s[TM];
    __shared__ float gsc_s[TM];
    __shared__ int   off_s;
    extern __shared__ __align__(16) char dynraw[];

    int z  = blockIdx.z;
    int m0 = blockIdx.x * TM;
    int f0 = blockIdx.y * 128;
    int tid = threadIdx.x, wid = tid >> 5, lane = tid & 31;
    int warpM = wid >> 2, warpN = wid & 3;

    int cnt;
    const __half* W;
    if (z < N_EXP) {
        int c = g_cnt[z];
        if (m0 >= c) return;
        cnt = min(TM, c - m0);
        W   = g_eguw + (size_t)z * 2 * D_FF * D_MODEL;
        if (tid < TM) {
            if (tid < cnt) {
                tok_s[tid] = g_list[z * MAX_T + m0 + tid];
                gsc_s[tid] = g_gate[z * MAX_T + m0 + tid];
            } else { tok_s[tid] = 0; gsc_s[tid] = 0.f; }
        }
        if (wid == 0) {  // prefix: off = sum_{e<z} g_cnt[e]
            int v = (lane < z) ? g_cnt[lane] : 0;
#pragma unroll
            for (int o = 16; o; o >>= 1) v += __shfl_xor_sync(0xffffffffu, v, o);
            if (lane == 0) off_s = v;
        }
    } else {
        if (m0 >= T) return;
        cnt = min(TM, T - m0);
        W   = g_sguw;
        if (tid < TM) { tok_s[tid] = m0 + tid; gsc_s[tid] = 1.f; }
        if (tid == 0) off_s = 0;
    }
    __syncthreads();
    int hbase = (z < N_EXP) ? (MAX_T + off_s + m0) : m0;

    char*    dynp = (char*)(((uintptr_t)dynraw + 1023) & ~(uintptr_t)1023);
    uint32_t sb   = smem_u32(dynp);

    auto load_stage = [&](int s) {
        int kk = s * KC;
        uint32_t base = sb + (s % NSTG) * STAGE_B;
#pragma unroll
        for (int j = 0; j < 4; j++) {
            int w_ = tid + j * 256;
            int row = w_ >> 3, col = w_ & 7;
            uint32_t so = SWZ(row * 128 + col * 16);
            cp16(base + so, g_xw + (size_t)tok_s[row] * D_MODEL + kk + col * 8);
        }
#pragma unroll
        for (int j = 0; j < 8; j++) {
            int w_ = tid + j * 256;
            int row = w_ >> 3, col = w_ & 7;           // row 0..255
            uint32_t so = SWZ(row * 128 + col * 16);
            int wr = (row & 1) ? (D_FF + f0 + (row >> 1)) : (f0 + (row >> 1));
            cp16(base + OFF_B + so, W + (size_t)wr * D_MODEL + kk + col * 8);
        }
        CP_COMMIT();
    };

    float acc[4][8][4] = {};

    load_stage(0);
    load_stage(1);
    for (int s = 0; s < NCH; s++) {
        if (s + 2 < NCH)      { load_stage(s + 2); CP_WAIT(2); }
        else if (s + 1 < NCH) { CP_WAIT(1); }
        else                  { CP_WAIT(0); }
        __syncthreads();
        uint32_t base = sb + (s % NSTG) * STAGE_B;
#pragma unroll
        for (int ks = 0; ks < 4; ks++) {
            int kb = ks * 32 + (lane >> 4) * 16;
            uint32_t a[4][4], br[4][4];
            int arow = warpM * 64 + (lane & 15);
            int brow = warpN * 64 + (lane & 15);
#pragma unroll
            for (int h = 0; h < 4; h++)
                ldm4(br[h], base + OFF_B + SWZ((brow + h * 16) * 128 + kb));
#pragma unroll
            for (int mf = 0; mf < 4; mf++)
                ldm4(a[mf], base + SWZ((arow + mf * 16) * 128 + kb));
#pragma unroll
            for (int mf = 0; mf < 4; mf++)
#pragma unroll
                for (int h = 0; h < 4; h++)
#pragma unroll
                    for (int hf = 0; hf < 2; hf++)
                        mma16816(acc[mf][h * 2 + hf], a[mf], br[h][hf], br[h][hf + 2]);
        }
        __syncthreads();
    }

    // epilogue: (c even, c odd) = (gate, up) of one feature
#pragma unroll
    for (int mf = 0; mf < 4; mf++) {
        int rbase = warpM * 64 + mf * 16 + (lane >> 2);
#pragma unroll
        for (int rr = 0; rr < 2; rr++) {
            int r = rbase + rr * 8;
            if (r < cnt) {
                float gsc = gsc_s[r];
                size_t hrow = (size_t)(hbase + r) * D_FF;
#pragma unroll
                for (int h = 0; h < 4; h++)
#pragma unroll
                    for (int hf = 0; hf < 2; hf++) {
                        int nf = h * 2 + hf;
                        float g = acc[mf][nf][rr * 2 + 0];
                        float u = acc[mf][nf][rr * 2 + 1];
                        float hv = g / (1.f + __expf(-g)) * u * gsc;
                        int f = f0 + warpN * 32 + h * 8 + hf * 4 + (lane & 3);
                        g_H[hrow + f] = __float2half_rn(hv);
                    }
            }
        }
    }
}

// ---------------- GEMM 2: H @ Wd^T -> atomicAdd out ----------------
// Block: 128 rows x 256 output cols (256 B rows). Warp tile 64 x 64.
__global__ __launch_bounds__(256, 1) void down_mma(float* __restrict__ out, int T)
{
    __shared__ int tok_s[TM];
    __shared__ int off_s;
    extern __shared__ __align__(16) char dynraw[];

    int z  = blockIdx.z;
    int m0 = blockIdx.x * TM;
    int d0 = blockIdx.y * 256;
    int tid = threadIdx.x, wid = tid >> 5, lane = tid & 31;
    int warpM = wid >> 2, warpN = wid & 3;

    int cnt;
    const __half* W;
    if (z < N_EXP) {
        int c = g_cnt[z];
        if (m0 >= c) return;
        cnt = min(TM, c - m0);
        W   = g_ednw + (size_t)z * D_MODEL * D_FF;
        if (tid < TM) tok_s[tid] = (tid < cnt) ? g_list[z * MAX_T + m0 + tid] : 0;
        if (wid == 0) {
            int v = (lane < z) ? g_cnt[lane] : 0;
#pragma unroll
            for (int o = 16; o; o >>= 1) v += __shfl_xor_sync(0xffffffffu, v, o);
            if (lane == 0) off_s = v;
        }
    } else {
        if (m0 >= T) return;
        cnt = min(TM, T - m0);
        W   = g_sdnw;
        if (tid < TM) tok_s[tid] = m0 + tid;
        if (tid == 0) off_s = 0;
    }
    __syncthreads();
    int hbase = (z < N_EXP) ? (MAX_T + off_s + m0) : m0;

    char*    dynp = (char*)(((uintptr_t)dynraw + 1023) & ~(uintptr_t)1023);
    uint32_t sb   = smem_u32(dynp);

    auto load_stage = [&](int s) {
        int kk = s * KC;
        uint32_t base = sb + (s % NSTG) * STAGE_B;
#pragma unroll
        for (int j = 0; j < 4; j++) {
            int w_ = tid + j * 256;
            int row = w_ >> 3, col = w_ & 7;
            uint32_t so = SWZ(row * 128 + col * 16);
            cp16(base + so, g_H + (size_t)(hbase + row) * D_FF + kk + col * 8);
        }
#pragma unroll
        for (int j = 0; j < 8; j++) {
            int w_ = tid + j * 256;
            int row = w_ >> 3, col = w_ & 7;           // row 0..255
            uint32_t so = SWZ(row * 128 + col * 16);
            cp16(base + OFF_B + so, W + (size_t)(d0 + row) * D_FF + kk + col * 8);
        }
        CP_COMMIT();
    };

    float acc[4][8][4] = {};

    load_stage(0);
    load_stage(1);
    for (int s = 0; s < NCH; s++) {
        if (s + 2 < NCH)      { load_stage(s + 2); CP_WAIT(2); }
        else if (s + 1 < NCH) { CP_WAIT(1); }
        else                  { CP_WAIT(0); }
        __syncthreads();
        uint32_t base = sb + (s % NSTG) * STAGE_B;
#pragma unroll
        for (int ks = 0; ks < 4; ks++) {
            int kb = ks * 32 + (lane >> 4) * 16;
            uint32_t a[4][4], br[4][4];
            int arow = warpM * 64 + (lane & 15);
            int brow = warpN * 64 + (lane & 15);
#pragma unroll
            for (int h = 0; h < 4; h++)
                ldm4(br[h], base + OFF_B + SWZ((brow + h * 16) * 128 + kb));
#pragma unroll
            for (int mf = 0; mf < 4; mf++)
                ldm4(a[mf], base + SWZ((arow + mf * 16) * 128 + kb));
#pragma unroll
            for (int mf = 0; mf < 4; mf++)
#pragma unroll
                for (int h = 0; h < 4; h++)
#pragma unroll
                    for (int hf = 0; hf < 2; hf++)
                        mma16816(acc[mf][h * 2 + hf], a[mf], br[h][hf], br[h][hf + 2]);
        }
        __syncthreads();
    }

#pragma unroll
    for (int mf = 0; mf < 4; mf++) {
        int rbase = warpM * 64 + mf * 16 + (lane >> 2);
#pragma unroll
        for (int rr = 0; rr < 2; rr++) {
            int r = rbase + rr * 8;
            if (r < cnt) {
                float* orow = out + (size_t)tok_s[r] * D_MODEL;
#pragma unroll
                for (int h = 0; h < 4; h++)
#pragma unroll
                    for (int hf = 0; hf < 2; hf++) {
                        int nf = h * 2 + hf;
                        int c  = d0 + warpN * 64 + h * 16 + hf * 8 + (lane & 3) * 2;
                        atomicAdd(orow + c,     acc[mf][nf][rr * 2 + 0]);
                        atomicAdd(orow + c + 1, acc[mf][nf][rr * 2 + 1]);
                    }
            }
        }
    }
}

// ---------------- launch ----------------
extern "C" void kernel_launch(void* const* d_in, const int* in_sizes, int n_in,
                              void* d_out, int out_size)
{
    const float* x    = (const float*)d_in[0];
    const float* gw   = (const float*)d_in[1];
    const float* bias = (const float*)d_in[2];
    const float* sgu  = (const float*)d_in[3];
    const float* sdn  = (const float*)d_in[4];
    const float* egu  = (const float*)d_in[5];
    const float* edn  = (const float*)d_in[6];
    float* out = (float*)d_out;
    int T = in_sizes[0] / D_MODEL;

    cudaFuncSetAttribute(gu_mma,   cudaFuncAttributeMaxDynamicSharedMemorySize, DYN_B);
    cudaFuncSetAttribute(down_mma, cudaFuncAttributeMaxDynamicSharedMemorySize, DYN_B);

    void *xw, *sguw, *sdnw, *eguw, *ednw;
    cudaGetSymbolAddress(&xw,   g_xw);
    cudaGetSymbolAddress(&sguw, g_sguw); cudaGetSymbolAddress(&sdnw, g_sdnw);
    cudaGetSymbolAddress(&eguw, g_eguw); cudaGetSymbolAddress(&ednw, g_ednw);

    int nx   = T * D_MODEL;
    int ngu  = 2 * D_FF * D_MODEL;
    int ndn  = D_MODEL * D_FF;
    int negu = N_EXP * 2 * D_FF * D_MODEL;
    int nedn = N_EXP * D_MODEL * D_FF;

    cudaStream_t s1;
    cudaStreamCreate(&s1);
    cudaEvent_t e0, e_gu, e_dn;
    cudaEventCreateWithFlags(&e0,   cudaEventDisableTiming);
    cudaEventCreateWithFlags(&e_gu, cudaEventDisableTiming);
    cudaEventCreateWithFlags(&e_dn, cudaEventDisableTiming);

    // fork FIRST: side stream starts conversions immediately, concurrent with
    // the router chain on the main stream
    cudaEventRecord(e0, 0);
    cudaStreamWaitEvent(s1, e0, 0);
    int ngu_tot = nx + ngu + negu;
    conv3_kernel<<<(ngu_tot / 16 + 255) / 256, 256, 0, s1>>>(
        x,   (__half*)xw,   nx,
        sgu, (__half*)sguw, ngu,
        egu, (__half*)eguw, negu);
    cudaEventRecord(e_gu, s1);
    conv3_kernel<<<((ndn + nedn) / 16 + 255) / 256, 256, 0, s1>>>(
        sdn, (__half*)sdnw, ndn,
        edn, (__half*)ednw, nedn,
        sdn, (__half*)sdnw, 0);
    cudaMemsetAsync(out, 0, (size_t)out_size * sizeof(float), s1);
    cudaEventRecord(e_dn, s1);

    // main stream: routing chain (hidden under conv_gu)
    reset_kernel<<<1, 32>>>();
    router_kernel<<<(T + 15) / 16, 512>>>(x, gw, bias, T);

    cudaStreamWaitEvent(0, e_gu, 0);
    gu_mma<<<dim3(MAX_T / TM, D_FF / 128, N_EXP + 1), 256, DYN_B>>>(T);

    cudaStreamWaitEvent(0, e_dn, 0);
    down_mma<<<dim3(MAX_T / TM, D_MODEL / 256, N_EXP + 1), 256, DYN_B>>>(out, T);

    cudaEventDestroy(e0);
    cudaEventDestroy(e_gu);
    cudaEventDestroy(e_dn);
    cudaStreamDestroy(s1);
}